// round 3
// baseline (speedup 1.0000x reference)
#include <cuda_runtime.h>
#include <cuda_bf16.h>
#include <math.h>

// ============================================================================
// EquivariantDecoder: 4 chained e3linear layers with gated nonlinearities.
//   L1: v_raw[16384,3840] -> gate -> h1[16384,1856]
//   L2: h1 -> gate -> h2
//   L3: h2 -> gate -> h1 (reuse)
//   L4: h1 -> out[16384,49]
// All math fp32; inner products use Blackwell packed fma.rn.f32x2 with
// row-pairs packed into 64-bit registers (2x FFMA pipe throughput).
// ============================================================================

typedef unsigned long long u64;

#define BROWS 16384
#define HD    1856
#define TB    8          // rows per CTA
#define NT    64         // threads per CTA
#define STR   10         // smem row-transposed stride (floats), even => LDS.64 aligned
#define STRH  5          // STR/2, in u64 units

// ---- f32x2 helpers ---------------------------------------------------------
__device__ __forceinline__ u64 ffma2(u64 a, u64 b, u64 c) {
    u64 d;
    asm("fma.rn.f32x2 %0, %1, %2, %3;" : "=l"(d) : "l"(a), "l"(b), "l"(c));
    return d;
}
__device__ __forceinline__ u64 pk1(float w) {
    u64 r;
    asm("mov.b64 %0, {%1, %1};" : "=l"(r) : "f"(w));
    return r;
}
__device__ __forceinline__ u64 pk2(float a, float b) {
    u64 r;
    asm("mov.b64 %0, {%1, %2};" : "=l"(r) : "f"(a), "f"(b));
    return r;
}
__device__ __forceinline__ float2 upk(u64 v) {
    float2 r;
    asm("mov.b64 {%0, %1}, %2;" : "=f"(r.x), "=f"(r.y) : "l"(v));
    return r;
}
__device__ __forceinline__ float sigf(float x) { return 1.0f / (1.0f + __expf(-x)); }

// ---- layer descriptor ------------------------------------------------------
struct LDesc {
    int in_dim;
    int mi[7];      // input multiplicity per l
    int in_off[7];  // input offset per l
    int woff[7];    // weight offset for l=1..6 blocks
    int wB_off;     // weight offset of the (256,0) gate block
};

// ---- intermediate buffers (device globals; no allocation allowed) ----------
__device__ float g_h1[(size_t)BROWS * HD];
__device__ float g_h2[(size_t)BROWS * HD];

// ---- per-l compute phase (l >= 1) ------------------------------------------
// NM = 2l+1, MO = output multiplicity (64 or 32).
// Thread map: ocol = tid&15 owns OPT consecutive output channels (vector LDG),
// rp = tid>>4 owns row-pair rp (rows 2rp, 2rp+1).
template <int NM, int MO>
__device__ __forceinline__ void phase_l(
    const float* __restrict__ wblk, int mi, float sc,
    int goff, int hoff,
    float* __restrict__ hout, int row0,
    const u64* __restrict__ sx64, const u64* __restrict__ sg64,
    float* __restrict__ sxs, int tid)
{
    constexpr int OPT = (MO == 64) ? 4 : 2;
    constexpr int OUTLEN = MO * NM;
    const int ocol = tid & 15;
    const int rp   = tid >> 4;   // 0..3

    u64 acc[OPT][NM];
#pragma unroll
    for (int j = 0; j < OPT; j++)
#pragma unroll
        for (int m = 0; m < NM; m++) acc[j][m] = 0ull;

    if (MO == 64) {
        const float4* wq = (const float4*)wblk;
#pragma unroll 2
        for (int i = 0; i < mi; i++) {
            float4 wv = __ldg(wq + i * 16 + ocol);
            u64 w0 = pk1(wv.x), w1 = pk1(wv.y), w2 = pk1(wv.z), w3 = pk1(wv.w);
#pragma unroll
            for (int m = 0; m < NM; m++) {
                u64 xv = sx64[(i * NM + m) * STRH + rp];
                acc[0][m] = ffma2(xv, w0, acc[0][m]);
                acc[1][m] = ffma2(xv, w1, acc[1][m]);
                acc[2][m] = ffma2(xv, w2, acc[2][m]);
                acc[3][m] = ffma2(xv, w3, acc[3][m]);
            }
        }
    } else {
        const float2* wp = (const float2*)wblk;
#pragma unroll 2
        for (int i = 0; i < mi; i++) {
            float2 wv = __ldg(wp + i * 16 + ocol);
            u64 w0 = pk1(wv.x), w1 = pk1(wv.y);
#pragma unroll
            for (int m = 0; m < NM; m++) {
                u64 xv = sx64[(i * NM + m) * STRH + rp];
                acc[0][m] = ffma2(xv, w0, acc[0][m]);
                acc[1][m] = ffma2(xv, w1, acc[1][m]);
            }
        }
    }

    __syncthreads();   // everyone done reading sxs (input tile); reuse as output stage

    const int o0 = ocol * OPT;
#pragma unroll
    for (int j = 0; j < OPT; j++) {
        float2 g = upk(sg64[(goff + o0 + j) * STRH + rp]);
#pragma unroll
        for (int m = 0; m < NM; m++) {
            float2 a = upk(acc[j][m]);
            sxs[(2 * rp)     * OUTLEN + (o0 + j) * NM + m] = a.x * sc * g.x;
            sxs[(2 * rp + 1) * OUTLEN + (o0 + j) * NM + m] = a.y * sc * g.y;
        }
    }
    __syncthreads();

    // coalesced flush to global
    for (int r = 0; r < TB; r++)
        for (int c = tid; c < OUTLEN; c += NT)
            hout[(size_t)(row0 + r) * HD + hoff + c] = sxs[r * OUTLEN + c];
    __syncthreads();
}

// ---- fused linear+gate layer kernel (layers 1-3) ---------------------------
__global__ __launch_bounds__(NT) void layer_kernel(
    const float* __restrict__ xin, const float* __restrict__ w,
    float* __restrict__ hout, LDesc d)
{
    __shared__ __align__(16) float sxs[832 * STR];   // 33280 B
    __shared__ __align__(16) float sgs[256 * STR];   // 10240 B
    u64* sx64 = (u64*)sxs;
    u64* sg64 = (u64*)sgs;

    const int tid  = threadIdx.x;
    const int row0 = blockIdx.x * TB;

    // ============ Phase A: l=0 block -> 64 silu scalars + 256 sigmoid gates
    {
        const int mi0 = d.mi[0];
        for (int r = 0; r < TB; r++)
            for (int c = tid; c < mi0; c += NT)
                sxs[c * STR + r] = xin[(size_t)(row0 + r) * d.in_dim + c];
        __syncthreads();

        const int ocol = tid;                 // 0..63
        const float*  wA  = w;                          // (mi0 x 64) scalar block
        const float4* wB4 = (const float4*)(w + d.wB_off); // (mi0 x 256) gate block

        u64 acc[4][5];
#pragma unroll
        for (int p = 0; p < 4; p++)
#pragma unroll
            for (int k = 0; k < 5; k++) acc[p][k] = 0ull;

#pragma unroll 2
        for (int i = 0; i < mi0; i++) {
            float  wa = __ldg(wA + i * 64 + ocol);
            float4 wb = __ldg(wB4 + i * 64 + ocol);
            u64 w0 = pk1(wa), w1 = pk1(wb.x), w2 = pk1(wb.y), w3 = pk1(wb.z), w4 = pk1(wb.w);
#pragma unroll
            for (int p = 0; p < 4; p++) {
                u64 xv = sx64[i * STRH + p];
                acc[p][0] = ffma2(xv, w0, acc[p][0]);
                acc[p][1] = ffma2(xv, w1, acc[p][1]);
                acc[p][2] = ffma2(xv, w2, acc[p][2]);
                acc[p][3] = ffma2(xv, w3, acc[p][3]);
                acc[p][4] = ffma2(xv, w4, acc[p][4]);
            }
        }

        const float sc = rsqrtf((float)mi0);
#pragma unroll
        for (int p = 0; p < 4; p++) {
            float2 z = upk(acc[p][0]);
            float s0 = z.x * sc, s1 = z.y * sc;
            hout[(size_t)(row0 + 2 * p)     * HD + ocol] = s0 * sigf(s0); // silu
            hout[(size_t)(row0 + 2 * p + 1) * HD + ocol] = s1 * sigf(s1);
#pragma unroll
            for (int k = 1; k < 5; k++) {
                float2 zz = upk(acc[p][k]);
                sg64[(4 * ocol + (k - 1)) * STRH + p] = pk2(sigf(zz.x * sc), sigf(zz.y * sc));
            }
        }
        __syncthreads();
    }

    // ============ Phases l=1..6: linear + gate multiply
    auto load_x = [&](int off, int len) {
        for (int r = 0; r < TB; r++)
            for (int c = tid; c < len; c += NT)
                sxs[c * STR + r] = xin[(size_t)(row0 + r) * d.in_dim + off + c];
        __syncthreads();
    };

    load_x(d.in_off[1], d.mi[1] * 3);
    phase_l<3, 64>(w + d.woff[1], d.mi[1], rsqrtf((float)d.mi[1]), 0,   64,   hout, row0, sx64, sg64, sxs, tid);
    load_x(d.in_off[2], d.mi[2] * 5);
    phase_l<5, 64>(w + d.woff[2], d.mi[2], rsqrtf((float)d.mi[2]), 64,  256,  hout, row0, sx64, sg64, sxs, tid);
    load_x(d.in_off[3], d.mi[3] * 7);
    phase_l<7, 32>(w + d.woff[3], d.mi[3], rsqrtf((float)d.mi[3]), 128, 576,  hout, row0, sx64, sg64, sxs, tid);
    load_x(d.in_off[4], d.mi[4] * 9);
    phase_l<9, 32>(w + d.woff[4], d.mi[4], rsqrtf((float)d.mi[4]), 160, 800,  hout, row0, sx64, sg64, sxs, tid);
    load_x(d.in_off[5], d.mi[5] * 11);
    phase_l<11, 32>(w + d.woff[5], d.mi[5], rsqrtf((float)d.mi[5]), 192, 1088, hout, row0, sx64, sg64, sxs, tid);
    load_x(d.in_off[6], d.mi[6] * 13);
    phase_l<13, 32>(w + d.woff[6], d.mi[6], rsqrtf((float)d.mi[6]), 224, 1440, hout, row0, sx64, sg64, sxs, tid);
}

// ---- final projection layer (HID -> 49 outputs per row) --------------------
__global__ __launch_bounds__(256) void layer4_kernel(
    const float* __restrict__ h, const float* __restrict__ w4,
    float* __restrict__ out)
{
    const int warp = threadIdx.x >> 5;
    const int lane = threadIdx.x & 31;
    const int row  = blockIdx.x * 8 + warp;

    const float* hr = h + (size_t)row * HD;

    const int MI[7]   = {64, 64, 64, 32, 32, 32, 32};
    const int XOFF[7] = {0, 64, 256, 576, 800, 1088, 1440};
    const int WOFF[7] = {0, 64, 128, 192, 224, 256, 288};
    const int OOFF[7] = {0, 1, 4, 9, 16, 25, 36};

#pragma unroll
    for (int l = 0; l < 7; l++) {
        const int nm = 2 * l + 1;
        const int mi = MI[l];
        const float sc = rsqrtf((float)mi);
        for (int m = 0; m < nm; m++) {
            float s = 0.0f;
            for (int i = lane; i < mi; i += 32)
                s += hr[XOFF[l] + i * nm + m] * __ldg(w4 + WOFF[l] + i);
#pragma unroll
            for (int off = 16; off; off >>= 1)
                s += __shfl_xor_sync(0xFFFFFFFFu, s, off);
            if (lane == 0)
                out[(size_t)row * 49 + OOFF[l] + m] = s * sc;
        }
    }
}

// ---- launch ----------------------------------------------------------------
extern "C" void kernel_launch(void* const* d_in, const int* in_sizes, int n_in,
                              void* d_out, int out_size)
{
    const float* v  = (const float*)d_in[0];
    const float* w1 = (const float*)d_in[1];
    const float* w2 = (const float*)d_in[2];
    const float* w3 = (const float*)d_in[3];
    const float* w4 = (const float*)d_in[4];
    float* out = (float*)d_out;

    float *h1, *h2;
    cudaGetSymbolAddress((void**)&h1, g_h1);
    cudaGetSymbolAddress((void**)&h2, g_h2);

    LDesc d1;
    d1.in_dim = 3840;
    { int a[7] = {256, 128, 128, 64, 64, 64, 64};          for (int i = 0; i < 7; i++) d1.mi[i] = a[i]; }
    { int a[7] = {0, 256, 640, 1280, 1728, 2304, 3008};    for (int i = 0; i < 7; i++) d1.in_off[i] = a[i]; }
    { int a[7] = {0, 81920, 90112, 98304, 100352, 102400, 104448}; for (int i = 0; i < 7; i++) d1.woff[i] = a[i]; }
    d1.wB_off = 16384;

    LDesc dH;
    dH.in_dim = HD;
    { int a[7] = {64, 64, 64, 32, 32, 32, 32};             for (int i = 0; i < 7; i++) dH.mi[i] = a[i]; }
    { int a[7] = {0, 64, 256, 576, 800, 1088, 1440};       for (int i = 0; i < 7; i++) dH.in_off[i] = a[i]; }
    { int a[7] = {0, 20480, 24576, 28672, 29696, 30720, 31744};   for (int i = 0; i < 7; i++) dH.woff[i] = a[i]; }
    dH.wB_off = 4096;

    const int grid = BROWS / TB;       // 2048
    layer_kernel<<<grid, NT>>>(v,  w1, h1, d1);
    layer_kernel<<<grid, NT>>>(h1, w2, h2, dH);
    layer_kernel<<<grid, NT>>>(h2, w3, h1, dH);
    layer4_kernel<<<BROWS / 8, 256>>>(h1, w4, out);
}

// round 6
// speedup vs baseline: 1.1698x; 1.1698x over previous
#include <cuda_runtime.h>
#include <math.h>

// ============================================================================
// EquivariantDecoder — phase-specialized f32x2 FFMA implementation.
//   prep:    duplicate weights (w -> (w,w) pairs) once per launch
//   per layer (x3): gate_kernel (l=0 block -> silu scalars + sigmoid gates)
//                   + 6 phase_kernels (l=1..6 linear + gate multiply)
//   layer4_kernel: final projection to 49 outputs/row
// Inner loops are pure LDS.64 / LDG.128 / fma.rn.f32x2 (no pack movs).
// R4 fix: gate_kernel duplicated-weight row strides (wA: 32 ull2/row,
// wB: 128 ull2/row — previous round used the un-duplicated strides).
// ============================================================================

typedef unsigned long long u64;

#define BROWS 16384
#define HD    1856

__device__ __forceinline__ u64 ffma2(u64 a, u64 b, u64 c) {
    u64 d;
    asm("fma.rn.f32x2 %0, %1, %2, %3;" : "=l"(d) : "l"(a), "l"(b), "l"(c));
    return d;
}
__device__ __forceinline__ u64 pk2(float a, float b) {
    u64 r;
    asm("mov.b64 %0, {%1, %2};" : "=l"(r) : "f"(a), "f"(b));
    return r;
}
__device__ __forceinline__ float2 upk(u64 v) {
    float2 r;
    asm("mov.b64 {%0, %1}, %2;" : "=f"(r.x), "=f"(r.y) : "l"(v));
    return r;
}
__device__ __forceinline__ float sigf(float x) { return 1.0f / (1.0f + __expf(-x)); }

// ---- static device buffers (no allocation allowed) -------------------------
__device__ __align__(16) float g_h1[(size_t)BROWS * HD];
__device__ __align__(16) float g_h2[(size_t)BROWS * HD];
__device__ __align__(16) float g_gates[(size_t)BROWS * 256];  // [row-pair][256 gates][2 lanes]
__device__ __align__(16) float g_w1d[212992];                 // duplicated weights
__device__ __align__(16) float g_w2d[65536];
__device__ __align__(16) float g_w3d[65536];

// ---- weight duplication: wdup[2k] = wdup[2k+1] = w[k] ----------------------
__global__ void prep_kernel(const float* __restrict__ w1,
                            const float* __restrict__ w2,
                            const float* __restrict__ w3) {
    int k = blockIdx.x * 256 + threadIdx.x;
    if (k < 106496) { float v = w1[k]; g_w1d[2 * k] = v; g_w1d[2 * k + 1] = v; }
    if (k < 32768)  { float v = w2[k]; g_w2d[2 * k] = v; g_w2d[2 * k + 1] = v;
                      float u = w3[k]; g_w3d[2 * k] = u; g_w3d[2 * k + 1] = u; }
}

// ============================================================================
// gate_kernel: z[b, 0..319] = x[b, 0..MI0) @ (wA | wB); silu(z[:64]) -> h,
// sigmoid(z[64:320]) -> g_gates (row-pair packed).
// Geometry: 32 rows/CTA (16 row-pairs), 160 threads = 40 out-groups x 4 rp-groups.
// Each thread: 8 outputs x 4 row-pairs. Row-pairs live in f32x2 lanes.
// ============================================================================
template <int MI0>
__global__ __launch_bounds__(160) void gate_kernel(
    const float* __restrict__ xin, int in_dim,
    const float* __restrict__ wdA, const float* __restrict__ wdB,
    float* __restrict__ hout, float* __restrict__ gates, float sc)
{
    constexpr int STRIDE = 34;   // 32 rows + 2 pad (even -> aligned u64)
    __shared__ __align__(16) float sxs[MI0 * STRIDE];
    u64* sx64 = (u64*)sxs;

    const int tid = threadIdx.x;
    const int oc = tid % 40;     // 40 output groups of 8
    const int rg = tid / 40;     // 4 row-pair groups of 4
    const int row0 = blockIdx.x * 32;

    // load x tile, transposed [feature][row]
    for (int r = 0; r < 32; r++) {
        const float4* s4 = (const float4*)(xin + (size_t)(row0 + r) * in_dim);
        for (int c4 = tid; c4 < MI0 / 4; c4 += 160) {
            float4 v = __ldg(s4 + c4);
            sxs[(4 * c4 + 0) * STRIDE + r] = v.x;
            sxs[(4 * c4 + 1) * STRIDE + r] = v.y;
            sxs[(4 * c4 + 2) * STRIDE + r] = v.z;
            sxs[(4 * c4 + 3) * STRIDE + r] = v.w;
        }
    }
    __syncthreads();

    u64 acc[8][4];
#pragma unroll
    for (int k = 0; k < 8; k++)
#pragma unroll
        for (int j = 0; j < 4; j++) acc[k][j] = 0ull;

    const bool is_silu = (oc < 8);
    if (is_silu) {
        // wA row = 64 outputs duplicated = 128 floats = 32 ull2
        const ulonglong2* wr = (const ulonglong2*)wdA + oc * 4;
#pragma unroll 2
        for (int i = 0; i < MI0; i++) {
            u64 w[8];
#pragma unroll
            for (int q = 0; q < 4; q++) {
                ulonglong2 t = __ldg(wr + i * 32 + q);
                w[2 * q] = t.x; w[2 * q + 1] = t.y;
            }
#pragma unroll
            for (int j = 0; j < 4; j++) {
                u64 xv = sx64[i * 17 + (rg * 4 + j)];
#pragma unroll
                for (int k = 0; k < 8; k++) acc[k][j] = ffma2(xv, w[k], acc[k][j]);
            }
        }
    } else {
        // wB row = 256 outputs duplicated = 512 floats = 128 ull2
        const ulonglong2* wr = (const ulonglong2*)wdB + (oc - 8) * 4;
#pragma unroll 2
        for (int i = 0; i < MI0; i++) {
            u64 w[8];
#pragma unroll
            for (int q = 0; q < 4; q++) {
                ulonglong2 t = __ldg(wr + i * 128 + q);
                w[2 * q] = t.x; w[2 * q + 1] = t.y;
            }
#pragma unroll
            for (int j = 0; j < 4; j++) {
                u64 xv = sx64[i * 17 + (rg * 4 + j)];
#pragma unroll
                for (int k = 0; k < 8; k++) acc[k][j] = ffma2(xv, w[k], acc[k][j]);
            }
        }
    }

    if (is_silu) {
        const int o0 = oc * 8;
#pragma unroll
        for (int j = 0; j < 4; j++) {
            int r0 = row0 + (rg * 4 + j) * 2;
            float e0[8], e1[8];
#pragma unroll
            for (int k = 0; k < 8; k++) {
                float2 a = upk(acc[k][j]);
                float z0 = a.x * sc, z1 = a.y * sc;
                e0[k] = z0 * sigf(z0);
                e1[k] = z1 * sigf(z1);
            }
            float4* d0 = (float4*)(hout + (size_t)r0 * HD + o0);
            float4* d1 = (float4*)(hout + (size_t)(r0 + 1) * HD + o0);
            d0[0] = make_float4(e0[0], e0[1], e0[2], e0[3]);
            d0[1] = make_float4(e0[4], e0[5], e0[6], e0[7]);
            d1[0] = make_float4(e1[0], e1[1], e1[2], e1[3]);
            d1[1] = make_float4(e1[4], e1[5], e1[6], e1[7]);
        }
    } else {
        const int o0 = (oc - 8) * 8;
#pragma unroll
        for (int j = 0; j < 4; j++) {
            size_t bp = (size_t)(row0 / 2 + rg * 4 + j);
            u64 o[8];
#pragma unroll
            for (int k = 0; k < 8; k++) {
                float2 a = upk(acc[k][j]);
                o[k] = pk2(sigf(a.x * sc), sigf(a.y * sc));
            }
            ulonglong2* gp = (ulonglong2*)gates + (bp * 256 + o0) / 2;
#pragma unroll
            for (int q = 0; q < 4; q++)
                gp[q] = make_ulonglong2(o[2 * q], o[2 * q + 1]);
        }
    }
}

// ============================================================================
// phase_kernel<MI,NM,MO,TB>: y[b,o,m] = sc * g[b,o] * sum_i x[b,i,m] w[i,o]
// Geometry: TB rows/CTA, NT = 16*(TB/2) threads = 16 out-groups x TB/2 rp.
// Row-pairs in f32x2 lanes; OPT = MO/16 outputs per thread.
// ============================================================================
template <int MI, int NM, int MO, int TB>
__global__ __launch_bounds__(16 * (TB / 2)) void phase_kernel(
    const float* __restrict__ xin, int in_dim, int in_off,
    const float* __restrict__ wd, const float* __restrict__ gates,
    int goff, float* __restrict__ hout, int hoff, float sc)
{
    constexpr int OPT = MO / 16;
    constexpr int RPG = TB / 2;
    constexpr int NT = 16 * RPG;
    constexpr int FEATS = MI * NM;
    constexpr int STRIDE = TB + 2;
    constexpr int SH = STRIDE / 2;
    __shared__ __align__(16) float sxs[FEATS * STRIDE];
    u64* sx64 = (u64*)sxs;

    const int tid = threadIdx.x;
    const int oc = tid & 15;
    const int rp = tid >> 4;
    const int row0 = blockIdx.x * TB;

    // load x tile, transposed
    for (int r = 0; r < TB; r++) {
        const float4* s4 = (const float4*)(xin + (size_t)(row0 + r) * in_dim + in_off);
        for (int c4 = tid; c4 < FEATS / 4; c4 += NT) {
            float4 v = __ldg(s4 + c4);
            sxs[(4 * c4 + 0) * STRIDE + r] = v.x;
            sxs[(4 * c4 + 1) * STRIDE + r] = v.y;
            sxs[(4 * c4 + 2) * STRIDE + r] = v.z;
            sxs[(4 * c4 + 3) * STRIDE + r] = v.w;
        }
    }
    __syncthreads();

    u64 acc[OPT][NM];
#pragma unroll
    for (int j = 0; j < OPT; j++)
#pragma unroll
        for (int m = 0; m < NM; m++) acc[j][m] = 0ull;

    // wd row = MO outputs duplicated = 2*MO floats = MO u64 = MO/2 ull2
    const ulonglong2* wr = (const ulonglong2*)wd + (oc * OPT) / 2;
#pragma unroll 2
    for (int i = 0; i < MI; i++) {
        u64 w[OPT];
#pragma unroll
        for (int q = 0; q < OPT / 2; q++) {
            ulonglong2 t = __ldg(wr + i * (MO / 2) + q);
            w[2 * q] = t.x; w[2 * q + 1] = t.y;
        }
#pragma unroll
        for (int m = 0; m < NM; m++) {
            u64 xv = sx64[(i * NM + m) * SH + rp];
#pragma unroll
            for (int j = 0; j < OPT; j++) acc[j][m] = ffma2(xv, w[j], acc[j][m]);
        }
    }

    // gates for this thread's outputs (row-pair packed)
    u64 g[OPT];
    const u64* gp = (const u64*)gates + (size_t)(row0 / 2 + rp) * 256 + goff + oc * OPT;
#pragma unroll
    for (int j = 0; j < OPT; j++) g[j] = __ldg(gp + j);

    __syncthreads();   // done reading x; reuse sxs as output stage

#pragma unroll
    for (int j = 0; j < OPT; j++) {
        float2 gg = upk(g[j]);
#pragma unroll
        for (int m = 0; m < NM; m++) {
            float2 a = upk(acc[j][m]);
            int col = (oc * OPT + j) * NM + m;
            sxs[(2 * rp) * (MO * NM) + col]     = a.x * sc * gg.x;
            sxs[(2 * rp + 1) * (MO * NM) + col] = a.y * sc * gg.y;
        }
    }
    __syncthreads();

    constexpr int OUTF = MO * NM / 4;
    for (int r = 0; r < TB; r++) {
        float4* d = (float4*)(hout + (size_t)(row0 + r) * HD + hoff);
        const float4* s = (const float4*)(sxs + r * (MO * NM));
        for (int c = tid; c < OUTF; c += NT) d[c] = s[c];
    }
}

// ============================================================================
// layer4: final projection HID -> 49 per row
// ============================================================================
__global__ __launch_bounds__(256) void layer4_kernel(
    const float* __restrict__ h, const float* __restrict__ w4,
    float* __restrict__ out)
{
    const int warp = threadIdx.x >> 5;
    const int lane = threadIdx.x & 31;
    const int row  = blockIdx.x * 8 + warp;

    const float* hr = h + (size_t)row * HD;

    const int MI[7]   = {64, 64, 64, 32, 32, 32, 32};
    const int XOFF[7] = {0, 64, 256, 576, 800, 1088, 1440};
    const int WOFF[7] = {0, 64, 128, 192, 224, 256, 288};
    const int OOFF[7] = {0, 1, 4, 9, 16, 25, 36};

#pragma unroll
    for (int l = 0; l < 7; l++) {
        const int nm = 2 * l + 1;
        const int mi = MI[l];
        const float sc = rsqrtf((float)mi);
        for (int m = 0; m < nm; m++) {
            float s = 0.0f;
            for (int i = lane; i < mi; i += 32)
                s += hr[XOFF[l] + i * nm + m] * __ldg(w4 + WOFF[l] + i);
#pragma unroll
            for (int off = 16; off; off >>= 1)
                s += __shfl_xor_sync(0xFFFFFFFFu, s, off);
            if (lane == 0)
                out[(size_t)row * 49 + OOFF[l] + m] = s * sc;
        }
    }
}

// ---- launch ----------------------------------------------------------------
extern "C" void kernel_launch(void* const* d_in, const int* in_sizes, int n_in,
                              void* d_out, int out_size)
{
    const float* v  = (const float*)d_in[0];
    const float* w1 = (const float*)d_in[1];
    const float* w2 = (const float*)d_in[2];
    const float* w3 = (const float*)d_in[3];
    const float* w4 = (const float*)d_in[4];
    float* out = (float*)d_out;

    float *h1, *h2, *gt, *w1d, *w2d, *w3d;
    cudaGetSymbolAddress((void**)&h1,  g_h1);
    cudaGetSymbolAddress((void**)&h2,  g_h2);
    cudaGetSymbolAddress((void**)&gt,  g_gates);
    cudaGetSymbolAddress((void**)&w1d, g_w1d);
    cudaGetSymbolAddress((void**)&w2d, g_w2d);
    cudaGetSymbolAddress((void**)&w3d, g_w3d);

    const float s256 = 1.0f / sqrtf(256.0f);
    const float s128 = 1.0f / sqrtf(128.0f);
    const float s64  = 1.0f / sqrtf(64.0f);
    const float s32  = 1.0f / sqrtf(32.0f);

    prep_kernel<<<416, 256>>>(w1, w2, w3);

    const int G16 = BROWS / 16;   // 1024
    const int G8  = BROWS / 8;    // 2048
    const int G32 = BROWS / 32;   // 512

    // ---- layer 1: v(3840) -> h1
    gate_kernel<256><<<G32, 160>>>(v, 3840, w1d, w1d + 16384 * 2, h1, gt, s256);
    phase_kernel<128,  3, 64, 16><<<G16, 128>>>(v, 3840,  256, w1d +  81920 * 2, gt,   0, h1,   64, s128);
    phase_kernel<128,  5, 64, 16><<<G16, 128>>>(v, 3840,  640, w1d +  90112 * 2, gt,  64, h1,  256, s128);
    phase_kernel< 64,  7, 32, 16><<<G16, 128>>>(v, 3840, 1280, w1d +  98304 * 2, gt, 128, h1,  576, s64);
    phase_kernel< 64,  9, 32, 16><<<G16, 128>>>(v, 3840, 1728, w1d + 100352 * 2, gt, 160, h1,  800, s64);
    phase_kernel< 64, 11, 32,  8><<<G8,   64>>>(v, 3840, 2304, w1d + 102400 * 2, gt, 192, h1, 1088, s64);
    phase_kernel< 64, 13, 32,  8><<<G8,   64>>>(v, 3840, 3008, w1d + 104448 * 2, gt, 224, h1, 1440, s64);

    // ---- layer 2: h1 -> h2
    gate_kernel<64><<<G32, 160>>>(h1, HD, w2d, w2d + 4096 * 2, h2, gt, s64);
    phase_kernel<64,  3, 64, 16><<<G16, 128>>>(h1, HD,   64, w2d + 20480 * 2, gt,   0, h2,   64, s64);
    phase_kernel<64,  5, 64, 16><<<G16, 128>>>(h1, HD,  256, w2d + 24576 * 2, gt,  64, h2,  256, s64);
    phase_kernel<32,  7, 32, 16><<<G16, 128>>>(h1, HD,  576, w2d + 28672 * 2, gt, 128, h2,  576, s32);
    phase_kernel<32,  9, 32, 16><<<G16, 128>>>(h1, HD,  800, w2d + 29696 * 2, gt, 160, h2,  800, s32);
    phase_kernel<32, 11, 32, 16><<<G16, 128>>>(h1, HD, 1088, w2d + 30720 * 2, gt, 192, h2, 1088, s32);
    phase_kernel<32, 13, 32, 16><<<G16, 128>>>(h1, HD, 1440, w2d + 31744 * 2, gt, 224, h2, 1440, s32);

    // ---- layer 3: h2 -> h1
    gate_kernel<64><<<G32, 160>>>(h2, HD, w3d, w3d + 4096 * 2, h1, gt, s64);
    phase_kernel<64,  3, 64, 16><<<G16, 128>>>(h2, HD,   64, w3d + 20480 * 2, gt,   0, h1,   64, s64);
    phase_kernel<64,  5, 64, 16><<<G16, 128>>>(h2, HD,  256, w3d + 24576 * 2, gt,  64, h1,  256, s64);
    phase_kernel<32,  7, 32, 16><<<G16, 128>>>(h2, HD,  576, w3d + 28672 * 2, gt, 128, h1,  576, s32);
    phase_kernel<32,  9, 32, 16><<<G16, 128>>>(h2, HD,  800, w3d + 29696 * 2, gt, 160, h1,  800, s32);
    phase_kernel<32, 11, 32, 16><<<G16, 128>>>(h2, HD, 1088, w3d + 30720 * 2, gt, 192, h1, 1088, s32);
    phase_kernel<32, 13, 32, 16><<<G16, 128>>>(h2, HD, 1440, w3d + 31744 * 2, gt, 224, h1, 1440, s32);

    // ---- layer 4
    layer4_kernel<<<BROWS / 8, 256>>>(h1, w4, out);
}